// round 14
// baseline (speedup 1.0000x reference)
#include <cuda_runtime.h>

// BambooBase fused Coulomb(Ewald) + D3-CSO dispersion edge kernel.
// R14: 2 edges/thread (edges t and t+H, H=E/2 rounded to warp multiple) with
// ALL-SCALAR per-window access patterns identical to R13, gathers for both
// edges front-loaded (10-deep MLP/thread) to cover the idx->gather latency
// chain, and phase-split compute to bound live registers.

#define MAX_ATOMS 200064

__device__ float4 g_atom[MAX_ATOMS];

__device__ __forceinline__ float frcp(float x) { return __fdividef(1.0f, x); }

__global__ __launch_bounds__(512) void pack_atoms_kernel(
    const float* __restrict__ charge,
    const float* __restrict__ c6,
    const float* __restrict__ r0,
    int N)
{
    const float SQRT_ELE = 18.222615f;   // sqrt(332.0637)
    int t = blockIdx.x * blockDim.x + threadIdx.x;
    int base = 4 * t;
    if (base + 3 < N) {
        float4 q  = *(const float4*)(charge + base);
        float4 cc = *(const float4*)(c6 + base);
        float4 rr = *(const float4*)(r0 + base);
        g_atom[base + 0] = make_float4(q.x * SQRT_ELE, sqrtf(cc.x), 1.25f * rr.x, 0.f);
        g_atom[base + 1] = make_float4(q.y * SQRT_ELE, sqrtf(cc.y), 1.25f * rr.y, 0.f);
        g_atom[base + 2] = make_float4(q.z * SQRT_ELE, sqrtf(cc.z), 1.25f * rr.z, 0.f);
        g_atom[base + 3] = make_float4(q.w * SQRT_ELE, sqrtf(cc.w), 1.25f * rr.w, 0.f);
    } else {
        for (int i = base; i < N; ++i) {
            g_atom[i] = make_float4(charge[i] * SQRT_ELE, sqrtf(c6[i]), 1.25f * r0[i], 0.f);
        }
    }
}

// Forward transpose (for stores): V[3k+c] = component c of lane k.
__device__ __forceinline__ float gatherV(float v0, float v1, float v2, int j)
{
    int k = j / 3;
    int c = j - 3 * k;
    float t0 = __shfl_sync(0xffffffffu, v0, k);
    float t1 = __shfl_sync(0xffffffffu, v1, k);
    float t2 = __shfl_sync(0xffffffffu, v2, k);
    return c == 0 ? t0 : (c == 1 ? t1 : t2);
}

// Full per-edge computation from loaded inputs; writes everything for edge i.
__device__ __forceinline__ void compute_and_store(
    int i, int wbase, int lane, bool full, bool act,
    float4 pa, float4 pb, float dx, float dy, float dz,
    float* __restrict__ out, int E)
{
    const float EWALD_F    = 1.12837917f;
    const float EWALD_P    = 0.3275911f;
    const float A0 = 0.254829592f, A1 = -0.284496736f, A2 = 1.421413741f,
                A3 = -1.453152027f, A4 = 1.061405429f;
    const float COUL_R0    = 2.2f;
    const float INV_R0     = 1.0f / 2.2f;
    const float BETA_OVER_R0 = 18.7f / 2.2f;
    const float INV_BETA   = 1.0f / 18.7f;
    const float G_EWALD    = 0.3f;
    const float R6_SHIFT   = 8303.765625f;
    const float INV_CUT6   = 1.0e-6f;

    float cfx = 0.f, cfy = 0.f, cfz = 0.f;
    float dfx = 0.f, dfy = 0.f, dfz = 0.f;

    if (act) {
        float r2   = dx*dx + dy*dy + dz*dz;
        float rinv = rsqrtf(r2);
        float rij  = r2 * rinv;
        float rinv2 = rinv * rinv;

        float prefactor = pa.x * pb.x * rinv;

        float x  = BETA_OVER_R0 * (rij - COUL_R0);
        float ex = __expf(x);
        float one_p_ex = 1.0f + ex;
        float inv_1pex = frcp(one_p_ex);
        float damp = ex * inv_1pex;
        float sp   = __logf(one_p_ex) * INV_BETA;
        float s    = rij * INV_R0 * frcp(1.0f + sp);

        float ecoul = prefactor * s;
        float fcoul = prefactor * damp * s * s;

        float grij  = G_EWALD * rij;
        float expm2 = __expf(-grij * grij);
        float t     = frcp(1.0f + EWALD_P * grij);
        float erfc  = t * (A0 + t * (A1 + t * (A2 + t * (A3 + t * A4)))) * expm2;

        ecoul += prefactor * (erfc - 1.0f);
        fcoul += prefactor * (erfc + EWALD_F * grij * expm2 - 1.0f);

        float cscale = fcoul * rinv2;
        cfx = dx * cscale; cfy = dy * cscale; cfz = dz * cscale;

        float c6ij = pa.y * pb.y;
        float r6pow = r2 * r2 * r2;
        float inv_r6 = frcp(r6pow + R6_SHIFT);

        float e   = __expf(rij - (pa.z + pb.z));
        float inv_1pe = frcp(1.0f + e);
        float cso = 0.85f + 0.82f * inv_1pe;

        float c6_inv_r6 = c6ij * inv_r6;
        float edisp = c6ij * INV_CUT6 - c6_inv_r6 * cso;

        float r5 = r2 * r2 * rij;
        float fdisp = -6.0f * c6ij * r5 * inv_r6 * inv_r6 * cso
                      - c6_inv_r6 * (0.82f * e * inv_1pe * inv_1pe);

        float dscale = fdisp * rinv;
        dfx = dx * dscale; dfy = dy * dscale; dfz = dz * dscale;

        __stcs(out + i, ecoul);
        __stcs(out + 4*E + i, edisp);
    }

    if (full) {
        {
            float* base = out + E + 3 * wbase;
            float u0 = gatherV(cfx, cfy, cfz, lane);
            float u1 = gatherV(cfx, cfy, cfz, lane + 32);
            float u2 = gatherV(cfx, cfy, cfz, lane + 64);
            __stcs(base + lane,      u0);
            __stcs(base + lane + 32, u1);
            __stcs(base + lane + 64, u2);
        }
        {
            float* base = out + 5*E + 3 * wbase;
            float u0 = gatherV(dfx, dfy, dfz, lane);
            float u1 = gatherV(dfx, dfy, dfz, lane + 32);
            float u2 = gatherV(dfx, dfy, dfz, lane + 64);
            __stcs(base + lane,      u0);
            __stcs(base + lane + 32, u1);
            __stcs(base + lane + 64, u2);
        }
    } else if (act) {
        int i3 = 3 * i;
        float* cf = out + E + i3;
        cf[0] = cfx; cf[1] = cfy; cf[2] = cfz;
        float* df = out + 5*E + i3;
        df[0] = dfx; df[1] = dfy; df[2] = dfz;
    }
}

__global__ __launch_bounds__(256) void bamboo_edge_kernel(
    const int* __restrict__ row,
    const int* __restrict__ col,
    const float* __restrict__ dij,
    float* __restrict__ out,
    int E, int H)
{
    int t = blockIdx.x * blockDim.x + threadIdx.x;
    int lane = t & 31;

    // edge A: i = t           (covers [0, H))
    // edge B: j = t + H       (covers [H, E))
    int iA = t;
    int iB = t + H;
    int wbA = iA - lane;
    int wbB = iB - lane;
    bool actA = (iA < H);
    bool actB = (iB < E);
    bool fullA = (wbA + 31 < H);
    bool fullB = (wbB + 31 < E);

    // ---- front-loaded loads for BOTH edges (max MLP) ----
    int rA = 0, cA = 0, rB = 0, cB = 0;
    if (actA) { rA = __ldcs(row + iA); cA = __ldcs(col + iA); }
    if (actB) { rB = __ldcs(row + iB); cB = __ldcs(col + iB); }

    float4 paA = make_float4(0,0,1,0), pbA = make_float4(0,0,1,0);
    float4 paB = make_float4(0,0,1,0), pbB = make_float4(0,0,1,0);
    if (actA) { paA = __ldg(&g_atom[rA]); pbA = __ldg(&g_atom[cA]); }
    if (actB) { paB = __ldg(&g_atom[rB]); pbB = __ldg(&g_atom[cB]); }

    float dxA = 1.f, dyA = 0.f, dzA = 0.f;
    float dxB = 1.f, dyB = 0.f, dzB = 0.f;
    if (actA) {
        int i3 = 3 * iA;
        dxA = __ldcs(dij + i3 + 0);
        dyA = __ldcs(dij + i3 + 1);
        dzA = __ldcs(dij + i3 + 2);
    }
    if (actB) {
        int i3 = 3 * iB;
        dxB = __ldcs(dij + i3 + 0);
        dyB = __ldcs(dij + i3 + 1);
        dzB = __ldcs(dij + i3 + 2);
    }

    // ---- phase 1: edge A complete, then phase 2: edge B ----
    compute_and_store(iA, wbA, lane, fullA, actA, paA, pbA, dxA, dyA, dzA, out, E);
    compute_and_store(iB, wbB, lane, fullB, actB, paB, pbB, dxB, dyB, dzB, out, E);
}

extern "C" void kernel_launch(void* const* d_in, const int* in_sizes, int n_in,
                              void* d_out, int out_size)
{
    const int*   row    = (const int*)d_in[0];
    const int*   col    = (const int*)d_in[1];
    const float* dij    = (const float*)d_in[2];
    const float* charge = (const float*)d_in[3];
    const float* c6     = (const float*)d_in[4];
    const float* r0     = (const float*)d_in[5];
    float* out = (float*)d_out;

    int E = in_sizes[0];
    int N = in_sizes[3];

    int packThreads = (N + 3) / 4;
    pack_atoms_kernel<<<(packThreads + 511) / 512, 512>>>(charge, c6, r0, N);

    // H = ceil(E/2) rounded up to a warp multiple, so edge-B windows stay aligned
    int H = ((E + 1) / 2 + 31) & ~31;
    bamboo_edge_kernel<<<(H + 255) / 256, 256>>>(row, col, dij, out, E, H);
}

// round 15
// speedup vs baseline: 1.0055x; 1.0055x over previous
#include <cuda_runtime.h>

// BambooBase fused Coulomb(Ewald) + D3-CSO dispersion edge kernel.
// R15: R13 structure (best), plus a branch-free specialized edge kernel for
// the E % 512 == 0 case (no act/full predicates, no tail path), selected at
// launch. General guarded kernel retained for arbitrary E. Pack kernel at
// 256 threads/CTA so the prologue uses all 148 SMs.

#define MAX_ATOMS 200064

__device__ float4 g_atom[MAX_ATOMS];

__device__ __forceinline__ float frcp(float x) { return __fdividef(1.0f, x); }

__global__ __launch_bounds__(256) void pack_atoms_kernel(
    const float* __restrict__ charge,
    const float* __restrict__ c6,
    const float* __restrict__ r0,
    int N)
{
    const float SQRT_ELE = 18.222615f;   // sqrt(332.0637)
    int t = blockIdx.x * blockDim.x + threadIdx.x;
    int base = 4 * t;
    if (base + 3 < N) {
        float4 q  = *(const float4*)(charge + base);
        float4 cc = *(const float4*)(c6 + base);
        float4 rr = *(const float4*)(r0 + base);
        g_atom[base + 0] = make_float4(q.x * SQRT_ELE, sqrtf(cc.x), 1.25f * rr.x, 0.f);
        g_atom[base + 1] = make_float4(q.y * SQRT_ELE, sqrtf(cc.y), 1.25f * rr.y, 0.f);
        g_atom[base + 2] = make_float4(q.z * SQRT_ELE, sqrtf(cc.z), 1.25f * rr.z, 0.f);
        g_atom[base + 3] = make_float4(q.w * SQRT_ELE, sqrtf(cc.w), 1.25f * rr.w, 0.f);
    } else {
        for (int i = base; i < N; ++i) {
            g_atom[i] = make_float4(charge[i] * SQRT_ELE, sqrtf(c6[i]), 1.25f * r0[i], 0.f);
        }
    }
}

// Forward transpose (for stores): V[3k+c] = component c of lane k.
__device__ __forceinline__ float gatherV(float v0, float v1, float v2, int j)
{
    int k = j / 3;
    int c = j - 3 * k;
    float t0 = __shfl_sync(0xffffffffu, v0, k);
    float t1 = __shfl_sync(0xffffffffu, v1, k);
    float t2 = __shfl_sync(0xffffffffu, v2, k);
    return c == 0 ? t0 : (c == 1 ? t1 : t2);
}

// Core per-edge math. Inputs loaded by caller; outputs by reference.
__device__ __forceinline__ void edge_math(
    float4 pa, float4 pb, float dx, float dy, float dz,
    float& ecoul, float& cfx, float& cfy, float& cfz,
    float& edisp, float& dfx, float& dfy, float& dfz)
{
    const float EWALD_F    = 1.12837917f;
    const float EWALD_P    = 0.3275911f;
    const float A0 = 0.254829592f, A1 = -0.284496736f, A2 = 1.421413741f,
                A3 = -1.453152027f, A4 = 1.061405429f;
    const float COUL_R0    = 2.2f;
    const float INV_R0     = 1.0f / 2.2f;
    const float BETA_OVER_R0 = 18.7f / 2.2f;
    const float INV_BETA   = 1.0f / 18.7f;
    const float G_EWALD    = 0.3f;
    const float R6_SHIFT   = 8303.765625f;      // 4.5^6
    const float INV_CUT6   = 1.0e-6f;

    float r2   = dx*dx + dy*dy + dz*dz;
    float rinv = rsqrtf(r2);
    float rij  = r2 * rinv;
    float rinv2 = rinv * rinv;

    // ---- Coulomb ----
    float prefactor = pa.x * pb.x * rinv;

    float x  = BETA_OVER_R0 * (rij - COUL_R0);
    float ex = __expf(x);
    float one_p_ex = 1.0f + ex;
    float inv_1pex = frcp(one_p_ex);
    float damp = ex * inv_1pex;
    float sp   = __logf(one_p_ex) * INV_BETA;
    float s    = rij * INV_R0 * frcp(1.0f + sp);

    ecoul = prefactor * s;
    float fcoul = prefactor * damp * s * s;

    float grij  = G_EWALD * rij;
    float expm2 = __expf(-grij * grij);
    float t     = frcp(1.0f + EWALD_P * grij);
    float erfc  = t * (A0 + t * (A1 + t * (A2 + t * (A3 + t * A4)))) * expm2;

    ecoul += prefactor * (erfc - 1.0f);
    fcoul += prefactor * (erfc + EWALD_F * grij * expm2 - 1.0f);

    float cscale = fcoul * rinv2;
    cfx = dx * cscale; cfy = dy * cscale; cfz = dz * cscale;

    // ---- Dispersion (D3-CSO) ----
    float c6ij = pa.y * pb.y;
    float r6pow = r2 * r2 * r2;
    float inv_r6 = frcp(r6pow + R6_SHIFT);

    float e   = __expf(rij - (pa.z + pb.z));
    float inv_1pe = frcp(1.0f + e);
    float cso = 0.85f + 0.82f * inv_1pe;

    float c6_inv_r6 = c6ij * inv_r6;
    edisp = c6ij * INV_CUT6 - c6_inv_r6 * cso;

    float r5 = r2 * r2 * rij;
    float fdisp = -6.0f * c6ij * r5 * inv_r6 * inv_r6 * cso
                  - c6_inv_r6 * (0.82f * e * inv_1pe * inv_1pe);

    float dscale = fdisp * rinv;
    dfx = dx * dscale; dfy = dy * dscale; dfz = dz * dscale;
}

// Branch-free kernel: requires gridDim.x * blockDim.x == E (E % 512 == 0).
__global__ __launch_bounds__(512) void bamboo_edge_kernel_exact(
    const int* __restrict__ row,
    const int* __restrict__ col,
    const float* __restrict__ dij,
    float* __restrict__ out,
    int E)
{
    int i = blockIdx.x * blockDim.x + threadIdx.x;
    int lane = threadIdx.x & 31;
    int wbase = i - lane;

    int r = __ldcs(row + i);
    int c = __ldcs(col + i);

    int i3 = 3 * i;
    float dx = __ldcs(dij + i3 + 0);
    float dy = __ldcs(dij + i3 + 1);
    float dz = __ldcs(dij + i3 + 2);

    float4 pa = __ldg(&g_atom[r]);
    float4 pb = __ldg(&g_atom[c]);

    float ecoul, cfx, cfy, cfz, edisp, dfx, dfy, dfz;
    edge_math(pa, pb, dx, dy, dz, ecoul, cfx, cfy, cfz, edisp, dfx, dfy, dfz);

    __stcs(out + i, ecoul);
    __stcs(out + 4*E + i, edisp);

    {
        float* base = out + E + 3 * wbase;
        float u0 = gatherV(cfx, cfy, cfz, lane);
        float u1 = gatherV(cfx, cfy, cfz, lane + 32);
        float u2 = gatherV(cfx, cfy, cfz, lane + 64);
        __stcs(base + lane,      u0);
        __stcs(base + lane + 32, u1);
        __stcs(base + lane + 64, u2);
    }
    {
        float* base = out + 5*E + 3 * wbase;
        float u0 = gatherV(dfx, dfy, dfz, lane);
        float u1 = gatherV(dfx, dfy, dfz, lane + 32);
        float u2 = gatherV(dfx, dfy, dfz, lane + 64);
        __stcs(base + lane,      u0);
        __stcs(base + lane + 32, u1);
        __stcs(base + lane + 64, u2);
    }
}

// General guarded kernel (any E) — R13 structure.
__global__ __launch_bounds__(512) void bamboo_edge_kernel_gen(
    const int* __restrict__ row,
    const int* __restrict__ col,
    const float* __restrict__ dij,
    float* __restrict__ out,
    int E)
{
    int i = blockIdx.x * blockDim.x + threadIdx.x;
    int lane = threadIdx.x & 31;
    int wbase = i - lane;
    bool full = (wbase + 31 < E);
    bool act  = (i < E);

    float ecoul = 0.f, cfx = 0.f, cfy = 0.f, cfz = 0.f;
    float edisp = 0.f, dfx = 0.f, dfy = 0.f, dfz = 0.f;

    if (act) {
        int r = __ldcs(row + i);
        int c = __ldcs(col + i);
        int i3 = 3 * i;
        float dx = __ldcs(dij + i3 + 0);
        float dy = __ldcs(dij + i3 + 1);
        float dz = __ldcs(dij + i3 + 2);
        float4 pa = __ldg(&g_atom[r]);
        float4 pb = __ldg(&g_atom[c]);

        edge_math(pa, pb, dx, dy, dz, ecoul, cfx, cfy, cfz, edisp, dfx, dfy, dfz);

        __stcs(out + i, ecoul);
        __stcs(out + 4*E + i, edisp);
    }

    if (full) {
        {
            float* base = out + E + 3 * wbase;
            float u0 = gatherV(cfx, cfy, cfz, lane);
            float u1 = gatherV(cfx, cfy, cfz, lane + 32);
            float u2 = gatherV(cfx, cfy, cfz, lane + 64);
            __stcs(base + lane,      u0);
            __stcs(base + lane + 32, u1);
            __stcs(base + lane + 64, u2);
        }
        {
            float* base = out + 5*E + 3 * wbase;
            float u0 = gatherV(dfx, dfy, dfz, lane);
            float u1 = gatherV(dfx, dfy, dfz, lane + 32);
            float u2 = gatherV(dfx, dfy, dfz, lane + 64);
            __stcs(base + lane,      u0);
            __stcs(base + lane + 32, u1);
            __stcs(base + lane + 64, u2);
        }
    } else if (act) {
        int i3 = 3 * i;
        float* cf = out + E + i3;
        cf[0] = cfx; cf[1] = cfy; cf[2] = cfz;
        float* df = out + 5*E + i3;
        df[0] = dfx; df[1] = dfy; df[2] = dfz;
    }
}

extern "C" void kernel_launch(void* const* d_in, const int* in_sizes, int n_in,
                              void* d_out, int out_size)
{
    const int*   row    = (const int*)d_in[0];
    const int*   col    = (const int*)d_in[1];
    const float* dij    = (const float*)d_in[2];
    const float* charge = (const float*)d_in[3];
    const float* c6     = (const float*)d_in[4];
    const float* r0     = (const float*)d_in[5];
    float* out = (float*)d_out;

    int E = in_sizes[0];
    int N = in_sizes[3];

    int packThreads = (N + 3) / 4;
    pack_atoms_kernel<<<(packThreads + 255) / 256, 256>>>(charge, c6, r0, N);

    if ((E & 511) == 0) {
        bamboo_edge_kernel_exact<<<E / 512, 512>>>(row, col, dij, out, E);
    } else {
        bamboo_edge_kernel_gen<<<(E + 511) / 512, 512>>>(row, col, dij, out, E);
    }
}

// round 16
// speedup vs baseline: 1.0094x; 1.0039x over previous
#include <cuda_runtime.h>

// BambooBase fused Coulomb(Ewald) + D3-CSO dispersion edge kernel.
// R16: fix R15's dispatch bug — E=4M is divisible by 256, not 512. The
// branch-free specialized kernel now triggers: 256-thread blocks (best
// measured block size), grid*block == E exactly, no act/full guards, no
// tail path, no zero-init. Guarded general kernel kept for other shapes.

#define MAX_ATOMS 200064

__device__ float4 g_atom[MAX_ATOMS];

__device__ __forceinline__ float frcp(float x) { return __fdividef(1.0f, x); }

__global__ __launch_bounds__(256) void pack_atoms_kernel(
    const float* __restrict__ charge,
    const float* __restrict__ c6,
    const float* __restrict__ r0,
    int N)
{
    const float SQRT_ELE = 18.222615f;   // sqrt(332.0637)
    int t = blockIdx.x * blockDim.x + threadIdx.x;
    int base = 4 * t;
    if (base + 3 < N) {
        float4 q  = *(const float4*)(charge + base);
        float4 cc = *(const float4*)(c6 + base);
        float4 rr = *(const float4*)(r0 + base);
        g_atom[base + 0] = make_float4(q.x * SQRT_ELE, sqrtf(cc.x), 1.25f * rr.x, 0.f);
        g_atom[base + 1] = make_float4(q.y * SQRT_ELE, sqrtf(cc.y), 1.25f * rr.y, 0.f);
        g_atom[base + 2] = make_float4(q.z * SQRT_ELE, sqrtf(cc.z), 1.25f * rr.z, 0.f);
        g_atom[base + 3] = make_float4(q.w * SQRT_ELE, sqrtf(cc.w), 1.25f * rr.w, 0.f);
    } else {
        for (int i = base; i < N; ++i) {
            g_atom[i] = make_float4(charge[i] * SQRT_ELE, sqrtf(c6[i]), 1.25f * r0[i], 0.f);
        }
    }
}

// Forward transpose (for stores): V[3k+c] = component c of lane k.
__device__ __forceinline__ float gatherV(float v0, float v1, float v2, int j)
{
    int k = j / 3;
    int c = j - 3 * k;
    float t0 = __shfl_sync(0xffffffffu, v0, k);
    float t1 = __shfl_sync(0xffffffffu, v1, k);
    float t2 = __shfl_sync(0xffffffffu, v2, k);
    return c == 0 ? t0 : (c == 1 ? t1 : t2);
}

// Core per-edge math. Inputs loaded by caller; outputs by reference.
__device__ __forceinline__ void edge_math(
    float4 pa, float4 pb, float dx, float dy, float dz,
    float& ecoul, float& cfx, float& cfy, float& cfz,
    float& edisp, float& dfx, float& dfy, float& dfz)
{
    const float EWALD_F    = 1.12837917f;
    const float EWALD_P    = 0.3275911f;
    const float A0 = 0.254829592f, A1 = -0.284496736f, A2 = 1.421413741f,
                A3 = -1.453152027f, A4 = 1.061405429f;
    const float COUL_R0    = 2.2f;
    const float INV_R0     = 1.0f / 2.2f;
    const float BETA_OVER_R0 = 18.7f / 2.2f;
    const float INV_BETA   = 1.0f / 18.7f;
    const float G_EWALD    = 0.3f;
    const float R6_SHIFT   = 8303.765625f;      // 4.5^6
    const float INV_CUT6   = 1.0e-6f;

    float r2   = dx*dx + dy*dy + dz*dz;
    float rinv = rsqrtf(r2);
    float rij  = r2 * rinv;
    float rinv2 = rinv * rinv;

    // ---- Coulomb ----
    float prefactor = pa.x * pb.x * rinv;

    float x  = BETA_OVER_R0 * (rij - COUL_R0);
    float ex = __expf(x);
    float one_p_ex = 1.0f + ex;
    float inv_1pex = frcp(one_p_ex);
    float damp = ex * inv_1pex;
    float sp   = __logf(one_p_ex) * INV_BETA;
    float s    = rij * INV_R0 * frcp(1.0f + sp);

    ecoul = prefactor * s;
    float fcoul = prefactor * damp * s * s;

    float grij  = G_EWALD * rij;
    float expm2 = __expf(-grij * grij);
    float t     = frcp(1.0f + EWALD_P * grij);
    float erfc  = t * (A0 + t * (A1 + t * (A2 + t * (A3 + t * A4)))) * expm2;

    ecoul += prefactor * (erfc - 1.0f);
    fcoul += prefactor * (erfc + EWALD_F * grij * expm2 - 1.0f);

    float cscale = fcoul * rinv2;
    cfx = dx * cscale; cfy = dy * cscale; cfz = dz * cscale;

    // ---- Dispersion (D3-CSO) ----
    float c6ij = pa.y * pb.y;
    float r6pow = r2 * r2 * r2;
    float inv_r6 = frcp(r6pow + R6_SHIFT);

    float e   = __expf(rij - (pa.z + pb.z));
    float inv_1pe = frcp(1.0f + e);
    float cso = 0.85f + 0.82f * inv_1pe;

    float c6_inv_r6 = c6ij * inv_r6;
    edisp = c6ij * INV_CUT6 - c6_inv_r6 * cso;

    float r5 = r2 * r2 * rij;
    float fdisp = -6.0f * c6ij * r5 * inv_r6 * inv_r6 * cso
                  - c6_inv_r6 * (0.82f * e * inv_1pe * inv_1pe);

    float dscale = fdisp * rinv;
    dfx = dx * dscale; dfy = dy * dscale; dfz = dz * dscale;
}

// Branch-free kernel: requires gridDim.x * blockDim.x == E (E % 256 == 0).
__global__ __launch_bounds__(256) void bamboo_edge_kernel_exact(
    const int* __restrict__ row,
    const int* __restrict__ col,
    const float* __restrict__ dij,
    float* __restrict__ out,
    int E)
{
    int i = blockIdx.x * blockDim.x + threadIdx.x;
    int lane = threadIdx.x & 31;
    int wbase = i - lane;

    int r = __ldcs(row + i);
    int c = __ldcs(col + i);

    int i3 = 3 * i;
    float dx = __ldcs(dij + i3 + 0);
    float dy = __ldcs(dij + i3 + 1);
    float dz = __ldcs(dij + i3 + 2);

    float4 pa = __ldg(&g_atom[r]);
    float4 pb = __ldg(&g_atom[c]);

    float ecoul, cfx, cfy, cfz, edisp, dfx, dfy, dfz;
    edge_math(pa, pb, dx, dy, dz, ecoul, cfx, cfy, cfz, edisp, dfx, dfy, dfz);

    __stcs(out + i, ecoul);
    __stcs(out + 4*E + i, edisp);

    {
        float* base = out + E + 3 * wbase;
        float u0 = gatherV(cfx, cfy, cfz, lane);
        float u1 = gatherV(cfx, cfy, cfz, lane + 32);
        float u2 = gatherV(cfx, cfy, cfz, lane + 64);
        __stcs(base + lane,      u0);
        __stcs(base + lane + 32, u1);
        __stcs(base + lane + 64, u2);
    }
    {
        float* base = out + 5*E + 3 * wbase;
        float u0 = gatherV(dfx, dfy, dfz, lane);
        float u1 = gatherV(dfx, dfy, dfz, lane + 32);
        float u2 = gatherV(dfx, dfy, dfz, lane + 64);
        __stcs(base + lane,      u0);
        __stcs(base + lane + 32, u1);
        __stcs(base + lane + 64, u2);
    }
}

// General guarded kernel (any E) — R13 structure.
__global__ __launch_bounds__(256) void bamboo_edge_kernel_gen(
    const int* __restrict__ row,
    const int* __restrict__ col,
    const float* __restrict__ dij,
    float* __restrict__ out,
    int E)
{
    int i = blockIdx.x * blockDim.x + threadIdx.x;
    int lane = threadIdx.x & 31;
    int wbase = i - lane;
    bool full = (wbase + 31 < E);
    bool act  = (i < E);

    float ecoul = 0.f, cfx = 0.f, cfy = 0.f, cfz = 0.f;
    float edisp = 0.f, dfx = 0.f, dfy = 0.f, dfz = 0.f;

    if (act) {
        int r = __ldcs(row + i);
        int c = __ldcs(col + i);
        int i3 = 3 * i;
        float dx = __ldcs(dij + i3 + 0);
        float dy = __ldcs(dij + i3 + 1);
        float dz = __ldcs(dij + i3 + 2);
        float4 pa = __ldg(&g_atom[r]);
        float4 pb = __ldg(&g_atom[c]);

        edge_math(pa, pb, dx, dy, dz, ecoul, cfx, cfy, cfz, edisp, dfx, dfy, dfz);

        __stcs(out + i, ecoul);
        __stcs(out + 4*E + i, edisp);
    }

    if (full) {
        {
            float* base = out + E + 3 * wbase;
            float u0 = gatherV(cfx, cfy, cfz, lane);
            float u1 = gatherV(cfx, cfy, cfz, lane + 32);
            float u2 = gatherV(cfx, cfy, cfz, lane + 64);
            __stcs(base + lane,      u0);
            __stcs(base + lane + 32, u1);
            __stcs(base + lane + 64, u2);
        }
        {
            float* base = out + 5*E + 3 * wbase;
            float u0 = gatherV(dfx, dfy, dfz, lane);
            float u1 = gatherV(dfx, dfy, dfz, lane + 32);
            float u2 = gatherV(dfx, dfy, dfz, lane + 64);
            __stcs(base + lane,      u0);
            __stcs(base + lane + 32, u1);
            __stcs(base + lane + 64, u2);
        }
    } else if (act) {
        int i3 = 3 * i;
        float* cf = out + E + i3;
        cf[0] = cfx; cf[1] = cfy; cf[2] = cfz;
        float* df = out + 5*E + i3;
        df[0] = dfx; df[1] = dfy; df[2] = dfz;
    }
}

extern "C" void kernel_launch(void* const* d_in, const int* in_sizes, int n_in,
                              void* d_out, int out_size)
{
    const int*   row    = (const int*)d_in[0];
    const int*   col    = (const int*)d_in[1];
    const float* dij    = (const float*)d_in[2];
    const float* charge = (const float*)d_in[3];
    const float* c6     = (const float*)d_in[4];
    const float* r0     = (const float*)d_in[5];
    float* out = (float*)d_out;

    int E = in_sizes[0];
    int N = in_sizes[3];

    int packThreads = (N + 3) / 4;
    pack_atoms_kernel<<<(packThreads + 255) / 256, 256>>>(charge, c6, r0, N);

    if ((E & 255) == 0) {
        bamboo_edge_kernel_exact<<<E / 256, 256>>>(row, col, dij, out, E);
    } else {
        bamboo_edge_kernel_gen<<<(E + 255) / 256, 256>>>(row, col, dij, out, E);
    }
}